// round 14
// baseline (speedup 1.0000x reference)
#include <cuda_runtime.h>
#include <stdint.h>

// StridedSlice: out[n,c,h,w] = x[n,c,2h,2w]
//   in : (8,128,512,512) f32  — even input row r (= output row r) lives at
//        byte offset r*4096 (uniform stride, planes included), length 2048 B.
//   out: (8,128,256,256) f32  — out row = 1 KB, 262144 rows.
//
// Fully engine-driven variant. Per block (256 thr): 16 x 2 KB cp.async.bulk
// reads (even rows) into SMEM via one mbarrier, register decimation
// (w stride 2), then ONE 16 KB cp.async.bulk store. Both DRAM streams are
// TMA coarse bursts; SM only shuffles SMEM.

#define SMEM_IN    0u        // 32 KB: 16 input rows x 2048 B (linear)
#define SMEM_OUT   32768u    // 16 KB: output tile (linear)
#define SMEM_MBAR  49152u
#define SMEM_TOTAL 49280u

__global__ __launch_bounds__(256) void strided_slice_kernel(
    const char* __restrict__ in, float4* __restrict__ out)
{
    extern __shared__ __align__(128) char smem[];
    uint32_t sb;
    asm("{ .reg .u64 x; cvta.to.shared.u64 x, %1; cvt.u32.u64 %0, x; }"
        : "=r"(sb) : "l"(smem));

    unsigned tid = threadIdx.x;
    unsigned w   = tid >> 5;
    unsigned t   = tid & 31u;
    unsigned R   = blockIdx.x << 4;   // first of 16 output rows (= even-row idx)

    // ---- init barrier, then issue 16 x 2 KB engine reads ----
    if (tid == 0) {
        asm volatile("mbarrier.init.shared.b64 [%0], 1;"
                     :: "r"(sb + SMEM_MBAR) : "memory");
    }
    __syncthreads();

    if (tid == 0) {
        asm volatile("mbarrier.arrive.expect_tx.shared.b64 _, [%0], 32768;"
                     :: "r"(sb + SMEM_MBAR) : "memory");
        const char* g = in + (size_t)R * 4096;
        #pragma unroll
        for (int i = 0; i < 16; i++) {
            asm volatile(
                "cp.async.bulk.shared::cta.global.mbarrier::complete_tx::bytes "
                "[%0], [%1], 2048, [%2];"
                :: "r"(sb + SMEM_IN + i * 2048u), "l"(g + (size_t)i * 4096),
                   "r"(sb + SMEM_MBAR) : "memory");
        }
    }

    // wait (acquire) for all 32 KB to land
    {
        uint32_t mbar = sb + SMEM_MBAR;
        asm volatile(
            "{\n\t"
            ".reg .pred P;\n\t"
            "WL_%=:\n\t"
            "mbarrier.try_wait.parity.acquire.cta.shared::cta.b64 P, [%0], 0, 0x989680;\n\t"
            "@P bra.uni WD_%=;\n\t"
            "bra.uni WL_%=;\n\t"
            "WD_%=:\n\t"
            "}" :: "r"(mbar) : "memory");
    }

    // ---- decimate: warp w handles local rows j0=2w, j0+1 ----
    {
        unsigned j0 = w << 1;
        const float4* i0 = (const float4*)(smem + SMEM_IN + j0 * 2048u);
        const float4* i1 = (const float4*)(smem + SMEM_IN + j0 * 2048u + 2048u);
        float4* o0 = (float4*)(smem + SMEM_OUT + j0 * 1024u);
        float4* o1 = (float4*)(smem + SMEM_OUT + j0 * 1024u + 1024u);
        unsigned t2 = t << 1;

        float4 a0 = i0[t2],      a1 = i0[t2 + 1];
        float4 a2 = i0[t2 + 64], a3 = i0[t2 + 65];
        float4 b0 = i1[t2],      b1 = i1[t2 + 1];
        float4 b2 = i1[t2 + 64], b3 = i1[t2 + 65];

        o0[t]      = make_float4(a0.x, a0.z, a1.x, a1.z);
        o0[32 + t] = make_float4(a2.x, a2.z, a3.x, a3.z);
        o1[t]      = make_float4(b0.x, b0.z, b1.x, b1.z);
        o1[32 + t] = make_float4(b2.x, b2.z, b3.x, b3.z);
    }

    __syncthreads();

    // ---- single 16 KB engine store ----
    if (tid == 0) {
        const float4* g = out + ((size_t)R << 6);
        asm volatile("fence.proxy.async.shared::cta;" ::: "memory");
        asm volatile("cp.async.bulk.global.shared::cta.bulk_group [%0], [%1], 16384;"
                     :: "l"(g), "r"(sb + SMEM_OUT) : "memory");
        asm volatile("cp.async.bulk.commit_group;" ::: "memory");
        asm volatile("cp.async.bulk.wait_group.read 0;" ::: "memory");
        asm volatile("mbarrier.inval.shared.b64 [%0];"
                     :: "r"(sb + SMEM_MBAR) : "memory");
    }
    __syncthreads();
}

extern "C" void kernel_launch(void* const* d_in, const int* in_sizes, int n_in,
                              void* d_out, int out_size)
{
    (void)in_sizes; (void)n_in; (void)out_size;
    const char* in  = (const char*)d_in[0];
    float4*     out = (float4*)d_out;

    static int smem_set = 0;
    if (!smem_set) {
        cudaFuncSetAttribute(strided_slice_kernel,
                             cudaFuncAttributeMaxDynamicSharedMemorySize,
                             SMEM_TOTAL);
        smem_set = 1;
    }

    // 262144 output rows / 16 per block = 16384 blocks of 256 threads
    strided_slice_kernel<<<16384, 256, SMEM_TOTAL>>>(in, out);
}

// round 15
// speedup vs baseline: 1.0865x; 1.0865x over previous
#include <cuda_runtime.h>
#include <stdint.h>

// StridedSlice: out[n,c,h,w] = x[n,c,2h,2w]
//   in : (8,128,512,512) f32   in row = 128 float4, plane = 65536 float4
//   out: (8,128,256,256) f32   out row = 64 float4, 262144 rows total
//
// FINAL (verified twice: ncu 108.5/108.9 us, DRAM 87.5-87.7%, occ 96%).
// Reads: SM-issued LDG.256 at 32 B lane stride — sector-exact (every DRAM
// sector fetched is fully consumed; read traffic at its 512 MiB floor) and
// massively parallel across ~4700 warps (chip-wide read MLP; engine-driven
// reads measured 10% slower, R14). Writes: each block stages its 16
// contiguous output rows (16 KB) in SMEM and drains them with ONE
// cp.async.bulk shared->global — coarse sequential bursts decoupled from
// load issue (best measured write path, R11 vs R2-R10).
// Total DRAM traffic = 768 MiB, the floor for this op.

__device__ __forceinline__ void ldg256(const float4* __restrict__ p,
                                       float4& v0, float4& v1)
{
    asm volatile("ld.global.v8.f32 {%0,%1,%2,%3,%4,%5,%6,%7}, [%8];"
                 : "=f"(v0.x), "=f"(v0.y), "=f"(v0.z), "=f"(v0.w),
                   "=f"(v1.x), "=f"(v1.y), "=f"(v1.z), "=f"(v1.w)
                 : "l"(p));
}

__global__ __launch_bounds__(256) void strided_slice_kernel(
    const float4* __restrict__ in, float4* __restrict__ out)
{
    __shared__ __align__(128) float4 tile[1024];   // 16 KB staging

    unsigned tid = threadIdx.x;
    unsigned w   = tid >> 5;        // warp 0..7
    unsigned t   = tid & 31u;

    unsigned R  = blockIdx.x << 4;  // first of 16 output rows for this block
    unsigned h  = R & 255u;         // multiple of 16; all rows in one plane
    unsigned nc = R >> 8;

    const float4* __restrict__ ib = in + ((size_t)nc << 16) + ((size_t)h << 8);

    unsigned j0 = w << 1;           // this warp's 2 local rows: j0, j0+1
    unsigned t2 = t << 1;

    // ---- load + decimate + stage (front-batched LDG.256) ----
    const float4* p0 = ib + j0 * 256;          // input row 2(h+j0)
    float4 a0, a1, a2, a3, b0, b1, b2, b3;
    ldg256(p0 + t2,        a0, a1);            // row j0,   out cols 0..31
    ldg256(p0 + t2 + 64,   a2, a3);            // row j0,   out cols 32..63
    ldg256(p0 + t2 + 256,  b0, b1);            // row j0+1, out cols 0..31
    ldg256(p0 + t2 + 320,  b2, b3);            // row j0+1, out cols 32..63

    float4* s = tile + j0 * 64;                // linear output layout in smem
    s[t]       = make_float4(a0.x, a0.z, a1.x, a1.z);
    s[32 + t]  = make_float4(a2.x, a2.z, a3.x, a3.z);
    s[64 + t]  = make_float4(b0.x, b0.z, b1.x, b1.z);
    s[96 + t]  = make_float4(b2.x, b2.z, b3.x, b3.z);

    __syncthreads();

    // ---- single 16 KB bulk store for the whole block ----
    if (tid == 0) {
        uint32_t saddr;
        asm("{ .reg .u64 x; cvta.to.shared.u64 x, %1; cvt.u32.u64 %0, x; }"
            : "=r"(saddr) : "l"(tile));
        const float4* g = out + ((size_t)R << 6);
        asm volatile("fence.proxy.async.shared::cta;" ::: "memory");
        asm volatile("cp.async.bulk.global.shared::cta.bulk_group [%0], [%1], 16384;"
                     :: "l"(g), "r"(saddr) : "memory");
        asm volatile("cp.async.bulk.commit_group;" ::: "memory");
        // release SMEM as soon as TMA has READ it (don't wait for write landing)
        asm volatile("cp.async.bulk.wait_group.read 0;" ::: "memory");
    }
    __syncthreads();   // no thread exits before SMEM is safe to retire
}

extern "C" void kernel_launch(void* const* d_in, const int* in_sizes, int n_in,
                              void* d_out, int out_size)
{
    (void)in_sizes; (void)n_in; (void)out_size;
    const float4* in  = (const float4*)d_in[0];
    float4*       out = (float4*)d_out;

    // 262144 output rows / 16 rows per block = 16384 blocks of 256 threads
    strided_slice_kernel<<<16384, 256>>>(in, out);
}

// round 16
// speedup vs baseline: 1.0870x; 1.0005x over previous
#include <cuda_runtime.h>
#include <stdint.h>

// StridedSlice: out[n,c,h,w] = x[n,c,2h,2w]
//   in : (8,128,512,512) f32   in row = 128 float4, plane = 65536 float4
//   out: (8,128,256,256) f32   out row = 64 float4, 262144 rows total
//
// Warp-autonomous TMA-store variant (no block barriers). Each warp owns 2
// consecutive output rows (2 KB contiguous in gmem): sector-exact LDG.256
// reads (32 B lane stride), decimate, stage 2 KB in SMEM (warp-private
// region), __syncwarp, then the elected lane issues ONE cp.async.bulk
// (shared->global, 2 KB). Stores issue as soon as each warp's data is
// ready — no cross-warp coupling — while the write stream stays
// engine-driven and burst-coarse.

__device__ __forceinline__ void ldg256(const float4* __restrict__ p,
                                       float4& v0, float4& v1)
{
    asm volatile("ld.global.v8.f32 {%0,%1,%2,%3,%4,%5,%6,%7}, [%8];"
                 : "=f"(v0.x), "=f"(v0.y), "=f"(v0.z), "=f"(v0.w),
                   "=f"(v1.x), "=f"(v1.y), "=f"(v1.z), "=f"(v1.w)
                 : "l"(p));
}

__global__ __launch_bounds__(256) void strided_slice_kernel(
    const float4* __restrict__ in, float4* __restrict__ out)
{
    __shared__ __align__(128) float4 tile[1024];   // 16 KB: 2 KB per warp

    unsigned tid = threadIdx.x;
    unsigned w   = tid >> 5;
    unsigned t   = tid & 31u;

    unsigned wg = (blockIdx.x << 3) + w;   // global warp id
    unsigned r0 = wg << 1;                 // first of this warp's 2 output rows
    unsigned h  = r0 & 255u;               // even; both rows in one plane
    unsigned nc = r0 >> 8;

    const float4* __restrict__ ib = in + ((size_t)nc << 16) + ((size_t)h << 8);
    unsigned t2 = t << 1;

    // ---- load + decimate (front-batched, sector-exact LDG.256) ----
    float4 a0, a1, a2, a3, b0, b1, b2, b3;
    ldg256(ib + t2,        a0, a1);        // row 2h,   out cols 0..31
    ldg256(ib + t2 + 64,   a2, a3);        // row 2h,   out cols 32..63
    ldg256(ib + t2 + 256,  b0, b1);        // row 2h+2, out cols 0..31
    ldg256(ib + t2 + 320,  b2, b3);        // row 2h+2, out cols 32..63

    // ---- stage into this warp's private 2 KB SMEM region ----
    float4* s = tile + (w << 7);           // warp w -> tile[128w .. 128w+127]
    s[t]       = make_float4(a0.x, a0.z, a1.x, a1.z);
    s[32 + t]  = make_float4(a2.x, a2.z, a3.x, a3.z);
    s[64 + t]  = make_float4(b0.x, b0.z, b1.x, b1.z);
    s[96 + t]  = make_float4(b2.x, b2.z, b3.x, b3.z);

    __syncwarp();

    // ---- warp-scoped 2 KB bulk store ----
    if (t == 0) {
        uint32_t saddr;
        asm("{ .reg .u64 x; cvta.to.shared.u64 x, %1; cvt.u32.u64 %0, x; }"
            : "=r"(saddr) : "l"(s));
        const float4* g = out + ((size_t)r0 << 6);
        asm volatile("fence.proxy.async.shared::cta;" ::: "memory");
        asm volatile("cp.async.bulk.global.shared::cta.bulk_group [%0], [%1], 2048;"
                     :: "l"(g), "r"(saddr) : "memory");
        asm volatile("cp.async.bulk.commit_group;" ::: "memory");
        // release SMEM once TMA has READ it (don't wait for write landing)
        asm volatile("cp.async.bulk.wait_group.read 0;" ::: "memory");
    }
    __syncwarp();   // warp doesn't retire its SMEM until the bulk read is done
}

extern "C" void kernel_launch(void* const* d_in, const int* in_sizes, int n_in,
                              void* d_out, int out_size)
{
    (void)in_sizes; (void)n_in; (void)out_size;
    const float4* in  = (const float4*)d_in[0];
    float4*       out = (float4*)d_out;

    // 262144 output rows / 2 rows per warp = 131072 warps = 16384 blocks of 256
    strided_slice_kernel<<<16384, 256>>>(in, out);
}